// round 2
// baseline (speedup 1.0000x reference)
#include <cuda_runtime.h>
#include <math.h>

// Problem constants
#define Bb 8
#define Nn 4096
#define Cc 256
#define Hh 8
#define Dd 32
#define HID 1024
#define Mrows (Bb * Nn)           // 32768
#define ROWSZ ((size_t)Mrows * Cc) // 8388608

typedef unsigned long long ull;

// ---------------- scratch (device globals; no allocations allowed) ---------
__device__ float g_xpos[ROWSZ];
__device__ float g_xln[ROWSZ];
__device__ float g_sln[ROWSZ];
__device__ float g_qkv[(size_t)Mrows * 3 * Cc];
__device__ float g_attnpre[ROWSZ];
__device__ float g_attnproj[ROWSZ];
__device__ float g_update[ROWSZ];
__device__ float g_hln[ROWSZ];
__device__ float g_fc1[(size_t)Mrows * HID];
__device__ float g_kv[Bb * Hh * Dd * Dd]; // 65536

// ---------------- helpers ---------------------------------------------------
__device__ __forceinline__ float2 block_sum2(float a, float b, float* sm) {
    #pragma unroll
    for (int o = 16; o > 0; o >>= 1) {
        a += __shfl_down_sync(0xffffffffu, a, o);
        b += __shfl_down_sync(0xffffffffu, b, o);
    }
    int w = threadIdx.x >> 5, l = threadIdx.x & 31;
    if (l == 0) { sm[w] = a; sm[8 + w] = b; }
    __syncthreads();
    if (w == 0) {
        a = sm[l & 7]; b = sm[8 + (l & 7)];
        #pragma unroll
        for (int o = 4; o > 0; o >>= 1) {
            a += __shfl_down_sync(0xffffffffu, a, o);
            b += __shfl_down_sync(0xffffffffu, b, o);
        }
        if (l == 0) { sm[16] = a; sm[17] = b; }
    }
    __syncthreads();
    return make_float2(sm[16], sm[17]);
}

__device__ __forceinline__ float phi_fn(float x) {
    return x > 0.f ? x + 1.f : expf(x);
}

// packed f32x2 fma: d = a*b + d (element-wise on packed pairs)
__device__ __forceinline__ void ffma2(ull& d, ull a, ull b) {
    asm("fma.rn.f32x2 %0, %1, %2, %0;" : "+l"(d) : "l"(a), "l"(b));
}
__device__ __forceinline__ ull dup_f32x2(float a) {
    ull r;
    asm("mov.b64 %0, {%1, %1};" : "=l"(r) : "f"(a));
    return r;
}

// ---------------- kernel 1: x_pos, LN1(x_pos), LN2(prev_state) -------------
__global__ void __launch_bounds__(256) ln_pre_kernel(
    const float* __restrict__ input_, const float* __restrict__ prev,
    const float* __restrict__ pos,
    const float* __restrict__ w1, const float* __restrict__ b1,
    const float* __restrict__ w2, const float* __restrict__ b2)
{
    __shared__ float sm[32];
    int r = blockIdx.x;
    int c = threadIdx.x;
    int n = r & (Nn - 1);
    size_t o = (size_t)r * Cc + c;

    float x = input_[o] + pos[(size_t)n * Cc + c];
    g_xpos[o] = x;
    float2 ss = block_sum2(x, x * x, sm);
    float mu = ss.x * (1.f / Cc);
    float var = ss.y * (1.f / Cc) - mu * mu;
    g_xln[o] = (x - mu) * rsqrtf(var + 1e-5f) * w1[c] + b1[c];

    float s = prev[o];
    ss = block_sum2(s, s * s, sm);
    mu = ss.x * (1.f / Cc);
    var = ss.y * (1.f / Cc) - mu * mu;
    g_sln[o] = (s - mu) * rsqrtf(var + 1e-5f) * w2[c] + b2[c];
}

// ---------------- generic tiled SGEMM (f32x2 packed): C = sum_p A_p@W_p^T ---
// A: [M,K] row-major. W: [Nt, ldw] row-major (torch Linear weight layout).
// act: 0 none, 1 exact gelu, 2 sigmoid. resid: C += v instead of C = v.
#define BM 128
#define BN 128
#define BKK 16
#define TM 8
#define TN 8

__global__ void __launch_bounds__(256, 2) sgemm_kernel(
    const float* __restrict__ A0, const float* __restrict__ A1,
    const float* __restrict__ W0, const float* __restrict__ W1,
    const float* __restrict__ bias, float* __restrict__ Cmat,
    int M, int Nt, int K, int ldw, int act, int resid)
{
    __shared__ float As[BKK][BM + 4];
    __shared__ float Bs[BKK][BN + 4];
    const int t = threadIdx.x;
    const int bm = blockIdx.y * BM;
    const int bn = blockIdx.x * BN;
    const int tr = (t >> 4) * TM;
    const int tc = (t & 15) * TN;

    // acc packed pairwise along N: acc2[i][j] holds (c[i][2j], c[i][2j+1])
    ull acc2[TM][TN / 2];
    #pragma unroll
    for (int i = 0; i < TM; i++)
        #pragma unroll
        for (int j = 0; j < TN / 2; j++) acc2[i][j] = 0ull;

    const int npairs = (A1 != nullptr) ? 2 : 1;
    for (int p = 0; p < npairs; p++) {
        const float* __restrict__ A = p ? A1 : A0;
        const float* __restrict__ W = p ? W1 : W0;
        for (int k0 = 0; k0 < K; k0 += BKK) {
            #pragma unroll
            for (int i = 0; i < 2; i++) {
                int f = t + i * 256;
                int row = f >> 2, kq = f & 3;
                float4 v = *reinterpret_cast<const float4*>(
                    &A[(size_t)(bm + row) * K + k0 + kq * 4]);
                As[kq * 4 + 0][row] = v.x;
                As[kq * 4 + 1][row] = v.y;
                As[kq * 4 + 2][row] = v.z;
                As[kq * 4 + 3][row] = v.w;
            }
            #pragma unroll
            for (int i = 0; i < 2; i++) {
                int f = t + i * 256;
                int row = f >> 2, kq = f & 3;
                float4 v = *reinterpret_cast<const float4*>(
                    &W[(size_t)(bn + row) * ldw + k0 + kq * 4]);
                Bs[kq * 4 + 0][row] = v.x;
                Bs[kq * 4 + 1][row] = v.y;
                Bs[kq * 4 + 2][row] = v.z;
                Bs[kq * 4 + 3][row] = v.w;
            }
            __syncthreads();
            #pragma unroll
            for (int kk = 0; kk < BKK; kk++) {
                float4 a0 = *reinterpret_cast<const float4*>(&As[kk][tr]);
                float4 a1 = *reinterpret_cast<const float4*>(&As[kk][tr + 4]);
                // b pairs come out of smem already packed (8B-aligned)
                ulonglong2 bA = *reinterpret_cast<const ulonglong2*>(&Bs[kk][tc]);
                ulonglong2 bB = *reinterpret_cast<const ulonglong2*>(&Bs[kk][tc + 4]);
                ull bp[4] = {bA.x, bA.y, bB.x, bB.y};
                ull ap[TM];
                ap[0] = dup_f32x2(a0.x); ap[1] = dup_f32x2(a0.y);
                ap[2] = dup_f32x2(a0.z); ap[3] = dup_f32x2(a0.w);
                ap[4] = dup_f32x2(a1.x); ap[5] = dup_f32x2(a1.y);
                ap[6] = dup_f32x2(a1.z); ap[7] = dup_f32x2(a1.w);
                #pragma unroll
                for (int i = 0; i < TM; i++)
                    #pragma unroll
                    for (int j = 0; j < TN / 2; j++)
                        ffma2(acc2[i][j], ap[i], bp[j]);
            }
            __syncthreads();
        }
    }

    #pragma unroll
    for (int i = 0; i < TM; i++) {
        int r = bm + tr + i;
        #pragma unroll
        for (int j = 0; j < TN / 2; j++) {
            union { ull u; float2 f; } cv;
            cv.u = acc2[i][j];
            #pragma unroll
            for (int q = 0; q < 2; q++) {
                int c = bn + tc + 2 * j + q;
                float v = (q == 0) ? cv.f.x : cv.f.y;
                if (bias) v += bias[c];
                if (act == 1) v = 0.5f * v * (1.f + erff(v * 0.70710678118654752f));
                else if (act == 2) v = 1.f / (1.f + expf(-v));
                size_t o = (size_t)r * Nt + c;
                if (resid) Cmat[o] += v;
                else       Cmat[o] = v;
            }
        }
    }
}

// ---------------- kv = sum_n phi(k)[n,d] * v[n,e], split over N chunks ------
__global__ void zero_kv_kernel() {
    int i = blockIdx.x * 1024 + threadIdx.x;
    g_kv[i] = 0.f;
}

__global__ void __launch_bounds__(256) kv_kernel() {
    const int bh = blockIdx.x;      // 0..63
    const int chunk = blockIdx.y;   // 0..15 -> 256 rows each
    const int b = bh >> 3, h = bh & 7;
    __shared__ float ks[32][33];
    __shared__ float vs[32][33];
    const int t = threadIdx.x;
    const int d = t >> 3;
    const int e0 = (t & 7) * 4;
    float acc[4] = {0.f, 0.f, 0.f, 0.f};
    const int nbase = chunk * 256;

    for (int nb = 0; nb < 256; nb += 32) {
        #pragma unroll
        for (int i = 0; i < 4; i++) {
            int idx = t + i * 256;
            int row = idx >> 5, col = idx & 31;
            size_t base = ((size_t)(b * Nn + nbase + nb + row)) * (3 * Cc) + h * Dd + col;
            float kvl = g_qkv[base + Cc];
            ks[row][col] = phi_fn(kvl);
            vs[row][col] = g_qkv[base + 2 * Cc];
        }
        __syncthreads();
        #pragma unroll
        for (int nn = 0; nn < 32; nn++) {
            float kd = ks[nn][d];
            #pragma unroll
            for (int j = 0; j < 4; j++)
                acc[j] = fmaf(kd, vs[nn][e0 + j], acc[j]);
        }
        __syncthreads();
    }
    #pragma unroll
    for (int j = 0; j < 4; j++)
        atomicAdd(&g_kv[(size_t)bh * (Dd * Dd) + d * Dd + e0 + j], acc[j]);
}

// ---------------- attn_pre[b,n,h*D+e] = sum_d phi(q)[d] * kv[b,h,d,e] -------
__global__ void __launch_bounds__(256) attn_kernel() {
    const int r = blockIdx.x;
    const int b = r >> 12; // / 4096
    const int c = threadIdx.x;
    __shared__ float pq[Cc];
    float q = g_qkv[(size_t)r * (3 * Cc) + c];
    pq[c] = phi_fn(q);
    __syncthreads();
    const int h = c >> 5, e = c & 31;
    const float* kvp = &g_kv[((size_t)(b * Hh + h)) * (Dd * Dd) + e];
    const float* pqh = &pq[h * Dd];
    float s = 0.f;
    #pragma unroll
    for (int d2 = 0; d2 < Dd; d2++)
        s = fmaf(pqh[d2], kvp[d2 * Dd], s);
    g_attnpre[(size_t)r * Cc + c] = s;
}

// ------- fused: output_mid, new_state (gate), LN3(output_mid) ---------------
__global__ void __launch_bounds__(256) fuse_mid_kernel(
    const float* __restrict__ prev,
    const float* __restrict__ w3, const float* __restrict__ b3,
    float* __restrict__ out, float* __restrict__ nstate)
{
    __shared__ float sm[32];
    int r = blockIdx.x;
    int c = threadIdx.x;
    size_t o = (size_t)r * Cc + c;
    float a = g_attnproj[o];
    float om = g_xpos[o] + a;
    out[o] = om;
    float u = g_update[o];
    nstate[o] = prev[o] * (1.f - u) + a * u;
    float2 ss = block_sum2(om, om * om, sm);
    float mu = ss.x * (1.f / Cc);
    float var = ss.y * (1.f / Cc) - mu * mu;
    g_hln[o] = (om - mu) * rsqrtf(var + 1e-5f) * w3[c] + b3[c];
}

// ---------------- launch ----------------------------------------------------
extern "C" void kernel_launch(void* const* d_in, const int* in_sizes, int n_in,
                              void* d_out, int out_size) {
    const float* input_   = (const float*)d_in[0];
    const float* prev     = (const float*)d_in[1];
    const float* pos      = (const float*)d_in[2];
    const float* n1w      = (const float*)d_in[3];
    const float* n1b      = (const float*)d_in[4];
    const float* n2w      = (const float*)d_in[5];
    const float* n2b      = (const float*)d_in[6];
    const float* n3w      = (const float*)d_in[7];
    const float* n3b      = (const float*)d_in[8];
    const float* qkv_iw   = (const float*)d_in[9];
    const float* qkv_sw   = (const float*)d_in[10];
    const float* proj_w   = (const float*)d_in[11];
    const float* proj_b   = (const float*)d_in[12];
    const float* gate_w   = (const float*)d_in[13];
    const float* gate_b   = (const float*)d_in[14];
    const float* fc1_w    = (const float*)d_in[15];
    const float* fc1_b    = (const float*)d_in[16];
    const float* fc2_w    = (const float*)d_in[17];
    const float* fc2_b    = (const float*)d_in[18];

    float* out    = (float*)d_out;
    float* nstate = out + (size_t)out_size / 2;

    float *p_xln, *p_sln, *p_qkv, *p_attnpre, *p_attnproj, *p_update, *p_hln, *p_fc1;
    cudaGetSymbolAddress((void**)&p_xln, g_xln);
    cudaGetSymbolAddress((void**)&p_sln, g_sln);
    cudaGetSymbolAddress((void**)&p_qkv, g_qkv);
    cudaGetSymbolAddress((void**)&p_attnpre, g_attnpre);
    cudaGetSymbolAddress((void**)&p_attnproj, g_attnproj);
    cudaGetSymbolAddress((void**)&p_update, g_update);
    cudaGetSymbolAddress((void**)&p_hln, g_hln);
    cudaGetSymbolAddress((void**)&p_fc1, g_fc1);

    // 1) x_pos + LN1 + LN2
    ln_pre_kernel<<<Mrows, 256>>>(input_, prev, pos, n1w, n1b, n2w, n2b);

    // 2) qkv = x_ln @ Wi^T + s_ln @ Ws^T   [M, 768]
    sgemm_kernel<<<dim3(768 / BN, Mrows / BM), 256>>>(
        p_xln, p_sln, qkv_iw, qkv_sw, nullptr, p_qkv,
        Mrows, 3 * Cc, Cc, Cc, 0, 0);

    // 3) kv[b,h,d,e]
    zero_kv_kernel<<<64, 1024>>>();
    kv_kernel<<<dim3(Bb * Hh, 16), 256>>>();

    // 4) attn_pre = phi_q @ kv
    attn_kernel<<<Mrows, 256>>>();

    // 5) proj
    sgemm_kernel<<<dim3(Cc / BN, Mrows / BM), 256>>>(
        p_attnpre, nullptr, proj_w, nullptr, proj_b, p_attnproj,
        Mrows, Cc, Cc, Cc, 0, 0);

    // 6) gate: update = sigmoid([input_, prev] @ gate_w^T + gate_b)
    sgemm_kernel<<<dim3(Cc / BN, Mrows / BM), 256>>>(
        input_, prev, gate_w, gate_w + Cc, gate_b, p_update,
        Mrows, Cc, Cc, 2 * Cc, 2, 0);

    // 7) output_mid -> d_out, new_state, LN3 -> g_hln
    fuse_mid_kernel<<<Mrows, 256>>>(prev, n3w, n3b, out, nstate);

    // 8) fc1 with exact-gelu epilogue
    sgemm_kernel<<<dim3(HID / BN, Mrows / BM), 256>>>(
        p_hln, nullptr, fc1_w, nullptr, fc1_b, p_fc1,
        Mrows, HID, Cc, Cc, 1, 0);

    // 9) fc2, accumulate into output residual
    sgemm_kernel<<<dim3(Cc / BN, Mrows / BM), 256>>>(
        p_fc1, nullptr, fc2_w, nullptr, fc2_b, out,
        Mrows, Cc, HID, HID, 0, 1);
}

// round 4
// speedup vs baseline: 1.5615x; 1.5615x over previous
#include <cuda_runtime.h>
#include <cstdint>
#include <math.h>

// Problem constants
#define Bb 8
#define Nn 4096
#define Cc 256
#define Hh 8
#define Dd 32
#define HID 1024
#define Mrows (Bb * Nn)            // 32768
#define ROWSZ ((size_t)Mrows * Cc) // 8388608

// ---------------- scratch (device globals; no allocations allowed) ---------
__device__ float g_xpos[ROWSZ];
__device__ float g_xln[ROWSZ];
__device__ float g_sln[ROWSZ];
__device__ float g_qkv[(size_t)Mrows * 3 * Cc];
__device__ float g_attnpre[ROWSZ];
__device__ float g_attnproj[ROWSZ];
__device__ float g_update[ROWSZ];
__device__ float g_hln[ROWSZ];
__device__ float g_fc1[(size_t)Mrows * HID];
__device__ float g_kv[Bb * Hh * Dd * Dd]; // 65536

// ---------------- misc helpers ----------------------------------------------
__device__ __forceinline__ float2 block_sum2(float a, float b, float* sm) {
    #pragma unroll
    for (int o = 16; o > 0; o >>= 1) {
        a += __shfl_down_sync(0xffffffffu, a, o);
        b += __shfl_down_sync(0xffffffffu, b, o);
    }
    int w = threadIdx.x >> 5, l = threadIdx.x & 31;
    if (l == 0) { sm[w] = a; sm[8 + w] = b; }
    __syncthreads();
    if (w == 0) {
        a = sm[l & 7]; b = sm[8 + (l & 7)];
        #pragma unroll
        for (int o = 4; o > 0; o >>= 1) {
            a += __shfl_down_sync(0xffffffffu, a, o);
            b += __shfl_down_sync(0xffffffffu, b, o);
        }
        if (l == 0) { sm[16] = a; sm[17] = b; }
    }
    __syncthreads();
    return make_float2(sm[16], sm[17]);
}

__device__ __forceinline__ float phi_fn(float x) {
    return x > 0.f ? x + 1.f : expf(x);
}

__device__ __forceinline__ uint32_t f2tf32(float x) {
    uint32_t r;
    asm("cvt.rna.tf32.f32 %0, %1;" : "=r"(r) : "f"(x));
    return r;
}

// tf32 m16n8k8 mma: D (f32x4) += A(tf32 x4) @ B(tf32 x2)
__device__ __forceinline__ void mma_tf32(
    float& c0, float& c1, float& c2, float& c3,
    uint32_t a0, uint32_t a1, uint32_t a2, uint32_t a3,
    uint32_t b0, uint32_t b1)
{
    asm volatile(
        "mma.sync.aligned.m16n8k8.row.col.f32.tf32.tf32.f32 "
        "{%0,%1,%2,%3}, {%4,%5,%6,%7}, {%8,%9}, {%0,%1,%2,%3};"
        : "+f"(c0), "+f"(c1), "+f"(c2), "+f"(c3)
        : "r"(a0), "r"(a1), "r"(a2), "r"(a3), "r"(b0), "r"(b1));
}

// ---------------- kernel 1: x_pos, LN1(x_pos), LN2(prev_state) -------------
__global__ void __launch_bounds__(256) ln_pre_kernel(
    const float* __restrict__ input_, const float* __restrict__ prev,
    const float* __restrict__ pos,
    const float* __restrict__ w1, const float* __restrict__ b1,
    const float* __restrict__ w2, const float* __restrict__ b2)
{
    __shared__ float sm[32];
    int r = blockIdx.x;
    int c = threadIdx.x;
    int n = r & (Nn - 1);
    size_t o = (size_t)r * Cc + c;

    float x = input_[o] + pos[(size_t)n * Cc + c];
    g_xpos[o] = x;
    float2 ss = block_sum2(x, x * x, sm);
    float mu = ss.x * (1.f / Cc);
    float var = ss.y * (1.f / Cc) - mu * mu;
    g_xln[o] = (x - mu) * rsqrtf(var + 1e-5f) * w1[c] + b1[c];

    float s = prev[o];
    ss = block_sum2(s, s * s, sm);
    mu = ss.x * (1.f / Cc);
    var = ss.y * (1.f / Cc) - mu * mu;
    g_sln[o] = (s - mu) * rsqrtf(var + 1e-5f) * w2[c] + b2[c];
}

// ---------------- tf32 mma.sync GEMM: C = sum_p A_p @ W_p^T (+bias,act) -----
// Block tile 128x128, warp grid 2x4 (warp tile 64x32), K chunk = 32.
// smem layout k-major with stride 129 (conflict-free STS, cheap frag LDS).
// act: 0 none, 1 exact gelu, 2 sigmoid. resid: C += v.
#define GBM 128
#define GBN 128
#define GKC 32
#define KSTR 129
#define BUFW (GKC * KSTR)          // words per buffer = 4128
#define GEMM_SMEM_BYTES (4 * BUFW * 4)  // A0,A1,B0,B1 = 66048 B

__global__ void __launch_bounds__(256) mma_gemm_kernel(
    const float* __restrict__ A0, const float* __restrict__ A1,
    const float* __restrict__ W0, const float* __restrict__ W1,
    const float* __restrict__ bias, float* __restrict__ Cmat,
    int Nt, int K, int ldw, int act, int resid)
{
    extern __shared__ uint32_t smw[];
    const int tid = threadIdx.x;
    const int bm = blockIdx.y * GBM;
    const int bn = blockIdx.x * GBN;
    const int wid = tid >> 5, lane = tid & 31;
    const int gid = lane >> 2, tig = lane & 3;
    const int wm = (wid >> 2) * 64;   // warp M offset in tile
    const int wn = (wid & 3) * 32;    // warp N offset in tile

    const int lrow = tid >> 3;        // 0..31 per 256 thr? no: tid>>3 = 0..31
    const int lseg = tid & 7;         // k segment (float4 index)

    float acc[4][4][4];
    #pragma unroll
    for (int mt = 0; mt < 4; mt++)
        #pragma unroll
        for (int nt = 0; nt < 4; nt++)
            #pragma unroll
            for (int q = 0; q < 4; q++) acc[mt][nt][q] = 0.f;

    const int kchunks = K / GKC;
    const int npairs = (A1 != nullptr) ? 2 : 1;
    const int nchunks = kchunks * npairs;

    // prefetch chunk 0
    float4 pa[4], pb[4];
    {
        const float* __restrict__ A = A0;
        const float* __restrict__ W = W0;
        #pragma unroll
        for (int i = 0; i < 4; i++) {
            int row = lrow + i * 32;
            pa[i] = *reinterpret_cast<const float4*>(&A[(size_t)(bm + row) * K + lseg * 4]);
            pb[i] = *reinterpret_cast<const float4*>(&W[(size_t)(bn + row) * ldw + lseg * 4]);
        }
    }

    for (int c = 0; c < nchunks; c++) {
        const int b = c & 1;
        uint32_t* abuf = &smw[b * BUFW];
        uint32_t* bbuf = &smw[2 * BUFW + b * BUFW];

        // store prefetched chunk (transposed, tf32)
        #pragma unroll
        for (int i = 0; i < 4; i++) {
            int row = lrow + i * 32;
            int k = lseg * 4;
            abuf[(k + 0) * KSTR + row] = f2tf32(pa[i].x);
            abuf[(k + 1) * KSTR + row] = f2tf32(pa[i].y);
            abuf[(k + 2) * KSTR + row] = f2tf32(pa[i].z);
            abuf[(k + 3) * KSTR + row] = f2tf32(pa[i].w);
            bbuf[(k + 0) * KSTR + row] = f2tf32(pb[i].x);
            bbuf[(k + 1) * KSTR + row] = f2tf32(pb[i].y);
            bbuf[(k + 2) * KSTR + row] = f2tf32(pb[i].z);
            bbuf[(k + 3) * KSTR + row] = f2tf32(pb[i].w);
        }
        __syncthreads();

        // prefetch next chunk while MMAs run
        if (c + 1 < nchunks) {
            int cn = c + 1;
            int p = cn / kchunks;
            int k0 = (cn - p * kchunks) * GKC;
            const float* __restrict__ A = p ? A1 : A0;
            const float* __restrict__ W = p ? W1 : W0;
            #pragma unroll
            for (int i = 0; i < 4; i++) {
                int row = lrow + i * 32;
                pa[i] = *reinterpret_cast<const float4*>(&A[(size_t)(bm + row) * K + k0 + lseg * 4]);
                pb[i] = *reinterpret_cast<const float4*>(&W[(size_t)(bn + row) * ldw + k0 + lseg * 4]);
            }
        }

        // MMA over the 4 k=8 steps of this chunk
        #pragma unroll
        for (int ks = 0; ks < 4; ks++) {
            const int kb = ks * 8;
            uint32_t af[4][4], bf[4][2];
            #pragma unroll
            for (int mt = 0; mt < 4; mt++) {
                int m0 = wm + mt * 16 + gid;
                af[mt][0] = abuf[(kb + tig) * KSTR + m0];
                af[mt][1] = abuf[(kb + tig) * KSTR + m0 + 8];
                af[mt][2] = abuf[(kb + tig + 4) * KSTR + m0];
                af[mt][3] = abuf[(kb + tig + 4) * KSTR + m0 + 8];
            }
            #pragma unroll
            for (int nt = 0; nt < 4; nt++) {
                int n0 = wn + nt * 8 + gid;
                bf[nt][0] = bbuf[(kb + tig) * KSTR + n0];
                bf[nt][1] = bbuf[(kb + tig + 4) * KSTR + n0];
            }
            #pragma unroll
            for (int mt = 0; mt < 4; mt++)
                #pragma unroll
                for (int nt = 0; nt < 4; nt++)
                    mma_tf32(acc[mt][nt][0], acc[mt][nt][1],
                             acc[mt][nt][2], acc[mt][nt][3],
                             af[mt][0], af[mt][1], af[mt][2], af[mt][3],
                             bf[nt][0], bf[nt][1]);
        }
        __syncthreads();
    }

    // epilogue
    #pragma unroll
    for (int mt = 0; mt < 4; mt++) {
        #pragma unroll
        for (int nt = 0; nt < 4; nt++) {
            int row0 = bm + wm + mt * 16 + gid;
            int col0 = bn + wn + nt * 8 + tig * 2;
            #pragma unroll
            for (int half = 0; half < 2; half++) {
                int r = row0 + half * 8;
                float v0 = acc[mt][nt][half * 2 + 0];
                float v1 = acc[mt][nt][half * 2 + 1];
                if (bias) { v0 += bias[col0]; v1 += bias[col0 + 1]; }
                if (act == 1) {
                    v0 = 0.5f * v0 * (1.f + erff(v0 * 0.70710678118654752f));
                    v1 = 0.5f * v1 * (1.f + erff(v1 * 0.70710678118654752f));
                } else if (act == 2) {
                    v0 = 1.f / (1.f + expf(-v0));
                    v1 = 1.f / (1.f + expf(-v1));
                }
                size_t o = (size_t)r * Nt + col0;
                if (resid) {
                    float2 old = *reinterpret_cast<const float2*>(&Cmat[o]);
                    v0 += old.x; v1 += old.y;
                }
                *reinterpret_cast<float2*>(&Cmat[o]) = make_float2(v0, v1);
            }
        }
    }
}

// ---------------- kv = sum_n phi(k)[n,d] * v[n,e] ---------------------------
__global__ void zero_kv_kernel() {
    int i = blockIdx.x * 1024 + threadIdx.x;
    g_kv[i] = 0.f;
}

__global__ void __launch_bounds__(256) kv_kernel() {
    const int bh = blockIdx.x;
    const int chunk = blockIdx.y;
    const int b = bh >> 3, h = bh & 7;
    __shared__ float ks[32][33];
    __shared__ float vs[32][33];
    const int t = threadIdx.x;
    const int d = t >> 3;
    const int e0 = (t & 7) * 4;
    float acc[4] = {0.f, 0.f, 0.f, 0.f};
    const int nbase = chunk * 256;

    for (int nb = 0; nb < 256; nb += 32) {
        #pragma unroll
        for (int i = 0; i < 4; i++) {
            int idx = t + i * 256;
            int row = idx >> 5, col = idx & 31;
            size_t base = ((size_t)(b * Nn + nbase + nb + row)) * (3 * Cc) + h * Dd + col;
            float kvl = g_qkv[base + Cc];
            ks[row][col] = phi_fn(kvl);
            vs[row][col] = g_qkv[base + 2 * Cc];
        }
        __syncthreads();
        #pragma unroll
        for (int nn = 0; nn < 32; nn++) {
            float kd = ks[nn][d];
            #pragma unroll
            for (int j = 0; j < 4; j++)
                acc[j] = fmaf(kd, vs[nn][e0 + j], acc[j]);
        }
        __syncthreads();
    }
    #pragma unroll
    for (int j = 0; j < 4; j++)
        atomicAdd(&g_kv[(size_t)bh * (Dd * Dd) + d * Dd + e0 + j], acc[j]);
}

// ---------------- attn_pre = phi(q) @ kv ------------------------------------
__global__ void __launch_bounds__(256) attn_kernel() {
    const int r = blockIdx.x;
    const int b = r >> 12;
    const int c = threadIdx.x;
    __shared__ float pq[Cc];
    float q = g_qkv[(size_t)r * (3 * Cc) + c];
    pq[c] = phi_fn(q);
    __syncthreads();
    const int h = c >> 5, e = c & 31;
    const float* kvp = &g_kv[((size_t)(b * Hh + h)) * (Dd * Dd) + e];
    const float* pqh = &pq[h * Dd];
    float s = 0.f;
    #pragma unroll
    for (int d2 = 0; d2 < Dd; d2++)
        s = fmaf(pqh[d2], kvp[d2 * Dd], s);
    g_attnpre[(size_t)r * Cc + c] = s;
}

// ------- fused: output_mid, new_state (gate), LN3(output_mid) ---------------
__global__ void __launch_bounds__(256) fuse_mid_kernel(
    const float* __restrict__ prev,
    const float* __restrict__ w3, const float* __restrict__ b3,
    float* __restrict__ out, float* __restrict__ nstate)
{
    __shared__ float sm[32];
    int r = blockIdx.x;
    int c = threadIdx.x;
    size_t o = (size_t)r * Cc + c;
    float a = g_attnproj[o];
    float om = g_xpos[o] + a;
    out[o] = om;
    float u = g_update[o];
    nstate[o] = prev[o] * (1.f - u) + a * u;
    float2 ss = block_sum2(om, om * om, sm);
    float mu = ss.x * (1.f / Cc);
    float var = ss.y * (1.f / Cc) - mu * mu;
    g_hln[o] = (om - mu) * rsqrtf(var + 1e-5f) * w3[c] + b3[c];
}

// ---------------- launch ----------------------------------------------------
extern "C" void kernel_launch(void* const* d_in, const int* in_sizes, int n_in,
                              void* d_out, int out_size) {
    const float* input_   = (const float*)d_in[0];
    const float* prev     = (const float*)d_in[1];
    const float* pos      = (const float*)d_in[2];
    const float* n1w      = (const float*)d_in[3];
    const float* n1b      = (const float*)d_in[4];
    const float* n2w      = (const float*)d_in[5];
    const float* n2b      = (const float*)d_in[6];
    const float* n3w      = (const float*)d_in[7];
    const float* n3b      = (const float*)d_in[8];
    const float* qkv_iw   = (const float*)d_in[9];
    const float* qkv_sw   = (const float*)d_in[10];
    const float* proj_w   = (const float*)d_in[11];
    const float* proj_b   = (const float*)d_in[12];
    const float* gate_w   = (const float*)d_in[13];
    const float* gate_b   = (const float*)d_in[14];
    const float* fc1_w    = (const float*)d_in[15];
    const float* fc1_b    = (const float*)d_in[16];
    const float* fc2_w    = (const float*)d_in[17];
    const float* fc2_b    = (const float*)d_in[18];

    float* out    = (float*)d_out;
    float* nstate = out + (size_t)out_size / 2;

    float *p_xln, *p_sln, *p_qkv, *p_attnpre, *p_attnproj, *p_update, *p_hln, *p_fc1;
    cudaGetSymbolAddress((void**)&p_xln, g_xln);
    cudaGetSymbolAddress((void**)&p_sln, g_sln);
    cudaGetSymbolAddress((void**)&p_qkv, g_qkv);
    cudaGetSymbolAddress((void**)&p_attnpre, g_attnpre);
    cudaGetSymbolAddress((void**)&p_attnproj, g_attnproj);
    cudaGetSymbolAddress((void**)&p_update, g_update);
    cudaGetSymbolAddress((void**)&p_hln, g_hln);
    cudaGetSymbolAddress((void**)&p_fc1, g_fc1);

    cudaFuncSetAttribute(mma_gemm_kernel,
                         cudaFuncAttributeMaxDynamicSharedMemorySize,
                         GEMM_SMEM_BYTES);

    // 1) x_pos + LN1 + LN2
    ln_pre_kernel<<<Mrows, 256>>>(input_, prev, pos, n1w, n1b, n2w, n2b);

    // 2) qkv = x_ln @ Wi^T + s_ln @ Ws^T   [M, 768]
    mma_gemm_kernel<<<dim3(768 / GBN, Mrows / GBM), 256, GEMM_SMEM_BYTES>>>(
        p_xln, p_sln, qkv_iw, qkv_sw, nullptr, p_qkv,
        3 * Cc, Cc, Cc, 0, 0);

    // 3) kv[b,h,d,e]
    zero_kv_kernel<<<64, 1024>>>();
    kv_kernel<<<dim3(Bb * Hh, 16), 256>>>();

    // 4) attn_pre = phi_q @ kv
    attn_kernel<<<Mrows, 256>>>();

    // 5) proj
    mma_gemm_kernel<<<dim3(Cc / GBN, Mrows / GBM), 256, GEMM_SMEM_BYTES>>>(
        p_attnpre, nullptr, proj_w, nullptr, proj_b, p_attnproj,
        Cc, Cc, Cc, 0, 0);

    // 6) gate: update = sigmoid([input_, prev] @ gate_w^T + gate_b)
    mma_gemm_kernel<<<dim3(Cc / GBN, Mrows / GBM), 256, GEMM_SMEM_BYTES>>>(
        input_, prev, gate_w, gate_w + Cc, gate_b, p_update,
        Cc, Cc, 2 * Cc, 2, 0);

    // 7) output_mid -> d_out, new_state, LN3 -> g_hln
    fuse_mid_kernel<<<Mrows, 256>>>(prev, n3w, n3b, out, nstate);

    // 8) fc1 with exact-gelu epilogue
    mma_gemm_kernel<<<dim3(HID / GBN, Mrows / GBM), 256, GEMM_SMEM_BYTES>>>(
        p_hln, nullptr, fc1_w, nullptr, fc1_b, p_fc1,
        HID, Cc, Cc, 1, 0);

    // 9) fc2, accumulate into output residual
    mma_gemm_kernel<<<dim3(Cc / GBN, Mrows / GBM), 256, GEMM_SMEM_BYTES>>>(
        p_fc1, nullptr, fc2_w, nullptr, fc2_b, out,
        Cc, HID, HID, 0, 1);
}

// round 5
// speedup vs baseline: 2.5435x; 1.6289x over previous
#include <cuda_runtime.h>
#include <cstdint>
#include <math.h>

// Problem constants
#define Bb 8
#define Nn 4096
#define Cc 256
#define Hh 8
#define Dd 32
#define HID 1024
#define Mrows (Bb * Nn)            // 32768
#define ROWSZ ((size_t)Mrows * Cc) // 8388608

// ---------------- scratch (device globals; no allocations allowed) ---------
__device__ float g_xpos[ROWSZ];
__device__ float g_xln[ROWSZ];
__device__ float g_sln[ROWSZ];
__device__ float g_qkv[(size_t)Mrows * 3 * Cc];
__device__ float g_attnpre[ROWSZ];
__device__ float g_attnproj[ROWSZ];
__device__ float g_update[ROWSZ];
__device__ float g_hln[ROWSZ];
__device__ float g_fc1[(size_t)Mrows * HID];
__device__ float g_kv[Bb * Hh * Dd * Dd]; // 65536

// ---------------- misc helpers ----------------------------------------------
__device__ __forceinline__ float2 block_sum2(float a, float b, float* sm) {
    #pragma unroll
    for (int o = 16; o > 0; o >>= 1) {
        a += __shfl_down_sync(0xffffffffu, a, o);
        b += __shfl_down_sync(0xffffffffu, b, o);
    }
    int w = threadIdx.x >> 5, l = threadIdx.x & 31;
    if (l == 0) { sm[w] = a; sm[8 + w] = b; }
    __syncthreads();
    if (w == 0) {
        a = sm[l & 7]; b = sm[8 + (l & 7)];
        #pragma unroll
        for (int o = 4; o > 0; o >>= 1) {
            a += __shfl_down_sync(0xffffffffu, a, o);
            b += __shfl_down_sync(0xffffffffu, b, o);
        }
        if (l == 0) { sm[16] = a; sm[17] = b; }
    }
    __syncthreads();
    return make_float2(sm[16], sm[17]);
}

__device__ __forceinline__ float phi_fn(float x) {
    return x > 0.f ? x + 1.f : expf(x);
}

__device__ __forceinline__ uint32_t f2tf32(float x) {
    uint32_t r;
    asm("cvt.rna.tf32.f32 %0, %1;" : "=r"(r) : "f"(x));
    return r;
}

__device__ __forceinline__ uint32_t smem_to_u32(const void* p) {
    uint32_t a;
    asm("{ .reg .u64 t; cvta.to.shared.u64 t, %1; cvt.u32.u64 %0, t; }"
        : "=r"(a) : "l"(p));
    return a;
}

__device__ __forceinline__ void cpasync16(uint32_t smem_addr, const void* gptr) {
    asm volatile("cp.async.cg.shared.global [%0], [%1], 16;"
        :: "r"(smem_addr), "l"(gptr) : "memory");
}
__device__ __forceinline__ void cpasync_commit() {
    asm volatile("cp.async.commit_group;" ::: "memory");
}
template <int N>
__device__ __forceinline__ void cpasync_wait() {
    asm volatile("cp.async.wait_group %0;" :: "n"(N) : "memory");
}

// tf32 m16n8k8 mma: D (f32x4) += A(tf32 x4) @ B(tf32 x2)
__device__ __forceinline__ void mma_tf32(
    float& c0, float& c1, float& c2, float& c3,
    uint32_t a0, uint32_t a1, uint32_t a2, uint32_t a3,
    uint32_t b0, uint32_t b1)
{
    asm volatile(
        "mma.sync.aligned.m16n8k8.row.col.f32.tf32.tf32.f32 "
        "{%0,%1,%2,%3}, {%4,%5,%6,%7}, {%8,%9}, {%0,%1,%2,%3};"
        : "+f"(c0), "+f"(c1), "+f"(c2), "+f"(c3)
        : "r"(a0), "r"(a1), "r"(a2), "r"(a3), "r"(b0), "r"(b1));
}

// ---------------- kernel 1: x_pos, LN1(x_pos), LN2(prev_state) -------------
__global__ void __launch_bounds__(256) ln_pre_kernel(
    const float* __restrict__ input_, const float* __restrict__ prev,
    const float* __restrict__ pos,
    const float* __restrict__ w1, const float* __restrict__ b1,
    const float* __restrict__ w2, const float* __restrict__ b2)
{
    __shared__ float sm[32];
    int r = blockIdx.x;
    int c = threadIdx.x;
    int n = r & (Nn - 1);
    size_t o = (size_t)r * Cc + c;

    float x = input_[o] + pos[(size_t)n * Cc + c];
    g_xpos[o] = x;
    float2 ss = block_sum2(x, x * x, sm);
    float mu = ss.x * (1.f / Cc);
    float var = ss.y * (1.f / Cc) - mu * mu;
    g_xln[o] = (x - mu) * rsqrtf(var + 1e-5f) * w1[c] + b1[c];

    float s = prev[o];
    ss = block_sum2(s, s * s, sm);
    mu = ss.x * (1.f / Cc);
    var = ss.y * (1.f / Cc) - mu * mu;
    g_sln[o] = (s - mu) * rsqrtf(var + 1e-5f) * w2[c] + b2[c];
}

// ---------------- tf32 mma.sync GEMM: C = sum_p A_p @ W_p^T (+bias,act) -----
// Block tile 128x128, warp grid 2x4 (warp tile 64x32), K chunk = 32.
// smem m-major [row][KP=36] fp32 (conflict-free frags: bank = 4*gid+tig),
// cp.async 2-stage pipeline, cvt.rna.tf32 applied after LDS.
// act: 0 none, 1 exact gelu, 2 sigmoid. resid: C += v.
#define GBM 128
#define GBN 128
#define GKC 32
#define KP 36
#define ABUFW (GBM * KP)               // 4608 words per buffer
#define GEMM_SMEM_BYTES (4 * ABUFW * 4) // A0,A1,B0,B1 = 73728 B

__global__ void __launch_bounds__(256) mma_gemm_kernel(
    const float* __restrict__ A0, const float* __restrict__ A1,
    const float* __restrict__ W0, const float* __restrict__ W1,
    const float* __restrict__ bias, float* __restrict__ Cmat,
    int Nt, int K, int ldw, int act, int resid)
{
    extern __shared__ float smf[];
    const uint32_t sbase = smem_to_u32(smf);
    const int tid = threadIdx.x;
    const int bm = blockIdx.y * GBM;
    const int bn = blockIdx.x * GBN;
    const int wid = tid >> 5, lane = tid & 31;
    const int gid = lane >> 2, tig = lane & 3;
    const int wm = (wid >> 2) * 64;
    const int wn = (wid & 3) * 32;

    float acc[4][4][4];
    #pragma unroll
    for (int mt = 0; mt < 4; mt++)
        #pragma unroll
        for (int nt = 0; nt < 4; nt++)
            #pragma unroll
            for (int q = 0; q < 4; q++) acc[mt][nt][q] = 0.f;

    const int kchunks = K / GKC;
    const int npairs = (A1 != nullptr) ? 2 : 1;
    const int nchunks = kchunks * npairs;

    // per-thread load coords: 1024 float4 per tile / 256 thr = 4 each
    const int lrow0 = tid >> 3;     // used with +32*i
    const int lseg = tid & 7;

    auto issue = [&](int c) {
        const int b = c & 1;
        const int p = c / kchunks;
        const int k0 = (c - p * kchunks) * GKC;
        const float* __restrict__ A = p ? A1 : A0;
        const float* __restrict__ W = p ? W1 : W0;
        #pragma unroll
        for (int i = 0; i < 4; i++) {
            int row = lrow0 + i * 32;
            uint32_t da = sbase + (uint32_t)((b * ABUFW + row * KP + lseg * 4) * 4);
            cpasync16(da, &A[(size_t)(bm + row) * K + k0 + lseg * 4]);
            uint32_t db = sbase + (uint32_t)(((2 + b) * ABUFW + row * KP + lseg * 4) * 4);
            cpasync16(db, &W[(size_t)(bn + row) * ldw + k0 + lseg * 4]);
        }
        cpasync_commit();
    };

    issue(0);

    for (int c = 0; c < nchunks; c++) {
        if (c + 1 < nchunks) {
            issue(c + 1);
            cpasync_wait<1>();
        } else {
            cpasync_wait<0>();
        }
        __syncthreads();

        const int b = c & 1;
        const float* Ab = &smf[b * ABUFW];
        const float* Bbuf = &smf[(2 + b) * ABUFW];

        #pragma unroll
        for (int ks = 0; ks < 4; ks++) {
            const int kb = ks * 8;
            uint32_t af[4][4], bf[4][2];
            #pragma unroll
            for (int mt = 0; mt < 4; mt++) {
                int m0 = wm + mt * 16 + gid;
                af[mt][0] = f2tf32(Ab[m0 * KP + kb + tig]);
                af[mt][1] = f2tf32(Ab[(m0 + 8) * KP + kb + tig]);
                af[mt][2] = f2tf32(Ab[m0 * KP + kb + tig + 4]);
                af[mt][3] = f2tf32(Ab[(m0 + 8) * KP + kb + tig + 4]);
            }
            #pragma unroll
            for (int nt = 0; nt < 4; nt++) {
                int n0 = wn + nt * 8 + gid;
                bf[nt][0] = f2tf32(Bbuf[n0 * KP + kb + tig]);
                bf[nt][1] = f2tf32(Bbuf[n0 * KP + kb + tig + 4]);
            }
            #pragma unroll
            for (int mt = 0; mt < 4; mt++)
                #pragma unroll
                for (int nt = 0; nt < 4; nt++)
                    mma_tf32(acc[mt][nt][0], acc[mt][nt][1],
                             acc[mt][nt][2], acc[mt][nt][3],
                             af[mt][0], af[mt][1], af[mt][2], af[mt][3],
                             bf[nt][0], bf[nt][1]);
        }
        __syncthreads();
    }

    // epilogue
    #pragma unroll
    for (int mt = 0; mt < 4; mt++) {
        #pragma unroll
        for (int nt = 0; nt < 4; nt++) {
            int row0 = bm + wm + mt * 16 + gid;
            int col0 = bn + wn + nt * 8 + tig * 2;
            #pragma unroll
            for (int half = 0; half < 2; half++) {
                int r = row0 + half * 8;
                float v0 = acc[mt][nt][half * 2 + 0];
                float v1 = acc[mt][nt][half * 2 + 1];
                if (bias) { v0 += bias[col0]; v1 += bias[col0 + 1]; }
                if (act == 1) {
                    v0 = 0.5f * v0 * (1.f + erff(v0 * 0.70710678118654752f));
                    v1 = 0.5f * v1 * (1.f + erff(v1 * 0.70710678118654752f));
                } else if (act == 2) {
                    v0 = 1.f / (1.f + expf(-v0));
                    v1 = 1.f / (1.f + expf(-v1));
                }
                size_t o = (size_t)r * Nt + col0;
                if (resid) {
                    float2 old = *reinterpret_cast<const float2*>(&Cmat[o]);
                    v0 += old.x; v1 += old.y;
                }
                *reinterpret_cast<float2*>(&Cmat[o]) = make_float2(v0, v1);
            }
        }
    }
}

// ---------------- kv = sum_n phi(k)[n,d] * v[n,e] ---------------------------
__global__ void zero_kv_kernel() {
    int i = blockIdx.x * 1024 + threadIdx.x;
    g_kv[i] = 0.f;
}

__global__ void __launch_bounds__(256) kv_kernel() {
    const int bh = blockIdx.x;
    const int chunk = blockIdx.y;
    const int b = bh >> 3, h = bh & 7;
    __shared__ float ks[32][33];
    __shared__ float vs[32][33];
    const int t = threadIdx.x;
    const int d = t >> 3;
    const int e0 = (t & 7) * 4;
    float acc[4] = {0.f, 0.f, 0.f, 0.f};
    const int nbase = chunk * 256;

    for (int nb = 0; nb < 256; nb += 32) {
        #pragma unroll
        for (int i = 0; i < 4; i++) {
            int idx = t + i * 256;
            int row = idx >> 5, col = idx & 31;
            size_t base = ((size_t)(b * Nn + nbase + nb + row)) * (3 * Cc) + h * Dd + col;
            float kvl = g_qkv[base + Cc];
            ks[row][col] = phi_fn(kvl);
            vs[row][col] = g_qkv[base + 2 * Cc];
        }
        __syncthreads();
        #pragma unroll
        for (int nn = 0; nn < 32; nn++) {
            float kd = ks[nn][d];
            #pragma unroll
            for (int j = 0; j < 4; j++)
                acc[j] = fmaf(kd, vs[nn][e0 + j], acc[j]);
        }
        __syncthreads();
    }
    #pragma unroll
    for (int j = 0; j < 4; j++)
        atomicAdd(&g_kv[(size_t)bh * (Dd * Dd) + d * Dd + e0 + j], acc[j]);
}

// ---------------- attn_pre = phi(q) @ kv ------------------------------------
__global__ void __launch_bounds__(256) attn_kernel() {
    const int r = blockIdx.x;
    const int b = r >> 12;
    const int c = threadIdx.x;
    __shared__ float pq[Cc];
    float q = g_qkv[(size_t)r * (3 * Cc) + c];
    pq[c] = phi_fn(q);
    __syncthreads();
    const int h = c >> 5, e = c & 31;
    const float* kvp = &g_kv[((size_t)(b * Hh + h)) * (Dd * Dd) + e];
    const float* pqh = &pq[h * Dd];
    float s = 0.f;
    #pragma unroll
    for (int d2 = 0; d2 < Dd; d2++)
        s = fmaf(pqh[d2], kvp[d2 * Dd], s);
    g_attnpre[(size_t)r * Cc + c] = s;
}

// ------- fused: output_mid, new_state (gate), LN3(output_mid) ---------------
__global__ void __launch_bounds__(256) fuse_mid_kernel(
    const float* __restrict__ prev,
    const float* __restrict__ w3, const float* __restrict__ b3,
    float* __restrict__ out, float* __restrict__ nstate)
{
    __shared__ float sm[32];
    int r = blockIdx.x;
    int c = threadIdx.x;
    size_t o = (size_t)r * Cc + c;
    float a = g_attnproj[o];
    float om = g_xpos[o] + a;
    out[o] = om;
    float u = g_update[o];
    nstate[o] = prev[o] * (1.f - u) + a * u;
    float2 ss = block_sum2(om, om * om, sm);
    float mu = ss.x * (1.f / Cc);
    float var = ss.y * (1.f / Cc) - mu * mu;
    g_hln[o] = (om - mu) * rsqrtf(var + 1e-5f) * w3[c] + b3[c];
}

// ---------------- launch ----------------------------------------------------
extern "C" void kernel_launch(void* const* d_in, const int* in_sizes, int n_in,
                              void* d_out, int out_size) {
    const float* input_   = (const float*)d_in[0];
    const float* prev     = (const float*)d_in[1];
    const float* pos      = (const float*)d_in[2];
    const float* n1w      = (const float*)d_in[3];
    const float* n1b      = (const float*)d_in[4];
    const float* n2w      = (const float*)d_in[5];
    const float* n2b      = (const float*)d_in[6];
    const float* n3w      = (const float*)d_in[7];
    const float* n3b      = (const float*)d_in[8];
    const float* qkv_iw   = (const float*)d_in[9];
    const float* qkv_sw   = (const float*)d_in[10];
    const float* proj_w   = (const float*)d_in[11];
    const float* proj_b   = (const float*)d_in[12];
    const float* gate_w   = (const float*)d_in[13];
    const float* gate_b   = (const float*)d_in[14];
    const float* fc1_w    = (const float*)d_in[15];
    const float* fc1_b    = (const float*)d_in[16];
    const float* fc2_w    = (const float*)d_in[17];
    const float* fc2_b    = (const float*)d_in[18];

    float* out    = (float*)d_out;
    float* nstate = out + (size_t)out_size / 2;

    float *p_xln, *p_sln, *p_qkv, *p_attnpre, *p_attnproj, *p_update, *p_hln, *p_fc1;
    cudaGetSymbolAddress((void**)&p_xln, g_xln);
    cudaGetSymbolAddress((void**)&p_sln, g_sln);
    cudaGetSymbolAddress((void**)&p_qkv, g_qkv);
    cudaGetSymbolAddress((void**)&p_attnpre, g_attnpre);
    cudaGetSymbolAddress((void**)&p_attnproj, g_attnproj);
    cudaGetSymbolAddress((void**)&p_update, g_update);
    cudaGetSymbolAddress((void**)&p_hln, g_hln);
    cudaGetSymbolAddress((void**)&p_fc1, g_fc1);

    cudaFuncSetAttribute(mma_gemm_kernel,
                         cudaFuncAttributeMaxDynamicSharedMemorySize,
                         GEMM_SMEM_BYTES);

    // 1) x_pos + LN1 + LN2
    ln_pre_kernel<<<Mrows, 256>>>(input_, prev, pos, n1w, n1b, n2w, n2b);

    // 2) qkv = x_ln @ Wi^T + s_ln @ Ws^T   [M, 768]
    mma_gemm_kernel<<<dim3(768 / GBN, Mrows / GBM), 256, GEMM_SMEM_BYTES>>>(
        p_xln, p_sln, qkv_iw, qkv_sw, nullptr, p_qkv,
        3 * Cc, Cc, Cc, 0, 0);

    // 3) kv[b,h,d,e]
    zero_kv_kernel<<<64, 1024>>>();
    kv_kernel<<<dim3(Bb * Hh, 16), 256>>>();

    // 4) attn_pre = phi_q @ kv
    attn_kernel<<<Mrows, 256>>>();

    // 5) proj
    mma_gemm_kernel<<<dim3(Cc / GBN, Mrows / GBM), 256, GEMM_SMEM_BYTES>>>(
        p_attnpre, nullptr, proj_w, nullptr, proj_b, p_attnproj,
        Cc, Cc, Cc, 0, 0);

    // 6) gate: update = sigmoid([input_, prev] @ gate_w^T + gate_b)
    mma_gemm_kernel<<<dim3(Cc / GBN, Mrows / GBM), 256, GEMM_SMEM_BYTES>>>(
        input_, prev, gate_w, gate_w + Cc, gate_b, p_update,
        Cc, Cc, 2 * Cc, 2, 0);

    // 7) output_mid -> d_out, new_state, LN3 -> g_hln
    fuse_mid_kernel<<<Mrows, 256>>>(prev, n3w, n3b, out, nstate);

    // 8) fc1 with exact-gelu epilogue
    mma_gemm_kernel<<<dim3(HID / GBN, Mrows / GBM), 256, GEMM_SMEM_BYTES>>>(
        p_hln, nullptr, fc1_w, nullptr, fc1_b, p_fc1,
        HID, Cc, Cc, 1, 0);

    // 9) fc2, accumulate into output residual
    mma_gemm_kernel<<<dim3(Cc / GBN, Mrows / GBM), 256, GEMM_SMEM_BYTES>>>(
        p_fc1, nullptr, fc2_w, nullptr, fc2_b, out,
        Cc, HID, HID, 0, 1);
}

// round 7
// speedup vs baseline: 3.4190x; 1.3442x over previous
#include <cuda_runtime.h>
#include <cuda_fp16.h>
#include <cstdint>
#include <math.h>

// Problem constants
#define Bb 8
#define Nn 4096
#define Cc 256
#define Hh 8
#define Dd 32
#define HID 1024
#define Mrows (Bb * Nn)            // 32768
#define ROWSZ ((size_t)Mrows * Cc) // 8388608

// ---------------- scratch (device globals; no allocations allowed) ---------
__device__ float  g_xpos[ROWSZ];
__device__ __half g_xlnh[ROWSZ];
__device__ __half g_slnh[ROWSZ];
__device__ __half g_xh[ROWSZ];     // input_ as fp16
__device__ __half g_sh[ROWSZ];     // prev_state as fp16
__device__ float  g_qkv[(size_t)Mrows * 3 * Cc];
__device__ __half g_attnpreh[ROWSZ];
__device__ float  g_attnproj[ROWSZ];
__device__ float  g_update[ROWSZ];
__device__ __half g_hlnh[ROWSZ];
__device__ __half g_fc1h[(size_t)Mrows * HID];
__device__ float  g_kv[Bb * Hh * Dd * Dd];
// fp16 weights, concatenated
#define WOFF_QKVI 0
#define WOFF_QKVS 196608
#define WOFF_PROJ 393216
#define WOFF_GATE 458752
#define WOFF_FC1  589824
#define WOFF_FC2  851968
#define WTOTAL    1114112
__device__ __half g_wh[WTOTAL];

// ---------------- misc helpers ----------------------------------------------
__device__ __forceinline__ float2 block_sum2(float a, float b, float* sm) {
    #pragma unroll
    for (int o = 16; o > 0; o >>= 1) {
        a += __shfl_down_sync(0xffffffffu, a, o);
        b += __shfl_down_sync(0xffffffffu, b, o);
    }
    int w = threadIdx.x >> 5, l = threadIdx.x & 31;
    if (l == 0) { sm[w] = a; sm[8 + w] = b; }
    __syncthreads();
    if (w == 0) {
        a = sm[l & 7]; b = sm[8 + (l & 7)];
        #pragma unroll
        for (int o = 4; o > 0; o >>= 1) {
            a += __shfl_down_sync(0xffffffffu, a, o);
            b += __shfl_down_sync(0xffffffffu, b, o);
        }
        if (l == 0) { sm[16] = a; sm[17] = b; }
    }
    __syncthreads();
    return make_float2(sm[16], sm[17]);
}

__device__ __forceinline__ float phi_fn(float x) {
    return x > 0.f ? x + 1.f : expf(x);
}

__device__ __forceinline__ uint32_t smem_to_u32(const void* p) {
    uint32_t a;
    asm("{ .reg .u64 t; cvta.to.shared.u64 t, %1; cvt.u32.u64 %0, t; }"
        : "=r"(a) : "l"(p));
    return a;
}

__device__ __forceinline__ void cpasync16(uint32_t smem_addr, const void* gptr) {
    asm volatile("cp.async.cg.shared.global [%0], [%1], 16;"
        :: "r"(smem_addr), "l"(gptr) : "memory");
}
__device__ __forceinline__ void cpasync_commit() {
    asm volatile("cp.async.commit_group;" ::: "memory");
}
template <int N>
__device__ __forceinline__ void cpasync_wait() {
    asm volatile("cp.async.wait_group %0;" :: "n"(N) : "memory");
}

// fp16 m16n8k16 mma: D (f32x4) += A(f16x2 x4) @ B(f16x2 x2)
__device__ __forceinline__ void mma_f16(
    float& c0, float& c1, float& c2, float& c3,
    uint32_t a0, uint32_t a1, uint32_t a2, uint32_t a3,
    uint32_t b0, uint32_t b1)
{
    asm volatile(
        "mma.sync.aligned.m16n8k16.row.col.f32.f16.f16.f32 "
        "{%0,%1,%2,%3}, {%4,%5,%6,%7}, {%8,%9}, {%0,%1,%2,%3};"
        : "+f"(c0), "+f"(c1), "+f"(c2), "+f"(c3)
        : "r"(a0), "r"(a1), "r"(a2), "r"(a3), "r"(b0), "r"(b1));
}

// ---------------- weight fp32 -> fp16 conversion ----------------------------
__global__ void __launch_bounds__(256) w2h_kernel(
    const float* __restrict__ src, __half* __restrict__ dst, int n4)
{
    int i = blockIdx.x * 256 + threadIdx.x;
    if (i < n4) {
        float4 v = reinterpret_cast<const float4*>(src)[i];
        __half2* d = reinterpret_cast<__half2*>(dst) + 2 * i;
        d[0] = __floats2half2_rn(v.x, v.y);
        d[1] = __floats2half2_rn(v.z, v.w);
    }
}

// ---------------- kernel 1: x_pos, LN1, LN2, fp16 copies ---------------------
__global__ void __launch_bounds__(256) ln_pre_kernel(
    const float* __restrict__ input_, const float* __restrict__ prev,
    const float* __restrict__ pos,
    const float* __restrict__ w1, const float* __restrict__ b1,
    const float* __restrict__ w2, const float* __restrict__ b2)
{
    __shared__ float sm[32];
    int r = blockIdx.x;
    int c = threadIdx.x;
    int n = r & (Nn - 1);
    size_t o = (size_t)r * Cc + c;

    float xin = input_[o];
    float x = xin + pos[(size_t)n * Cc + c];
    g_xpos[o] = x;
    g_xh[o] = __float2half_rn(xin);
    float2 ss = block_sum2(x, x * x, sm);
    float mu = ss.x * (1.f / Cc);
    float var = ss.y * (1.f / Cc) - mu * mu;
    g_xlnh[o] = __float2half_rn((x - mu) * rsqrtf(var + 1e-5f) * w1[c] + b1[c]);

    float s = prev[o];
    g_sh[o] = __float2half_rn(s);
    ss = block_sum2(s, s * s, sm);
    mu = ss.x * (1.f / Cc);
    var = ss.y * (1.f / Cc) - mu * mu;
    g_slnh[o] = __float2half_rn((s - mu) * rsqrtf(var + 1e-5f) * w2[c] + b2[c]);
}

// ---------------- fp16 mma GEMM: C = sum_p A_p @ W_p^T (+bias,act) ----------
// Block tile 128x128, warp grid 2x4 (warp tile 64x32), K chunk = 32 halves.
// smem m-major [row][KPh=40] fp16 (conflict-free frags: word = 20*gid+tig).
// act: 0 none, 1 exact gelu, 2 sigmoid. resid: C += v. outhalf: fp16 store.
#define GBM 128
#define GBN 128
#define GKC 32
#define KPh 40
#define HBUF (GBM * KPh)                 // 5120 halves per buffer
#define GEMM_SMEM_BYTES (4 * HBUF * 2)   // A0,A1,B0,B1 = 40960 B

__global__ void __launch_bounds__(256) mma_gemm_kernel(
    const __half* __restrict__ A0, const __half* __restrict__ A1,
    const __half* __restrict__ W0, const __half* __restrict__ W1,
    const float* __restrict__ bias, void* __restrict__ Cmat,
    int Nt, int K, int ldw, int act, int resid, int outhalf)
{
    extern __shared__ __half smh[];
    const uint32_t sbase = smem_to_u32(smh);
    const int tid = threadIdx.x;
    const int bm = blockIdx.y * GBM;
    const int bn = blockIdx.x * GBN;
    const int wid = tid >> 5, lane = tid & 31;
    const int gid = lane >> 2, tig = lane & 3;
    const int wm = (wid >> 2) * 64;
    const int wn = (wid & 3) * 32;

    float acc[4][4][4];
    #pragma unroll
    for (int mt = 0; mt < 4; mt++)
        #pragma unroll
        for (int nt = 0; nt < 4; nt++)
            #pragma unroll
            for (int q = 0; q < 4; q++) acc[mt][nt][q] = 0.f;

    const int kchunks = K / GKC;
    const int npairs = (A1 != nullptr) ? 2 : 1;
    const int nchunks = kchunks * npairs;

    auto issue = [&](int c) {
        const int buf = c & 1;
        const int p = c / kchunks;
        const int k0 = (c - p * kchunks) * GKC;
        const __half* __restrict__ A = p ? A1 : A0;
        const __half* __restrict__ W = p ? W1 : W0;
        #pragma unroll
        for (int i = 0; i < 2; i++) {
            int f = tid + i * 256;
            int row = f >> 2, seg = f & 3;
            uint32_t da = sbase + (uint32_t)((buf * HBUF + row * KPh + seg * 8) * 2);
            cpasync16(da, &A[(size_t)(bm + row) * K + k0 + seg * 8]);
            uint32_t db = sbase + (uint32_t)(((2 + buf) * HBUF + row * KPh + seg * 8) * 2);
            cpasync16(db, &W[(size_t)(bn + row) * ldw + k0 + seg * 8]);
        }
        cpasync_commit();
    };

    issue(0);

    for (int c = 0; c < nchunks; c++) {
        if (c + 1 < nchunks) {
            issue(c + 1);
            cpasync_wait<1>();
        } else {
            cpasync_wait<0>();
        }
        __syncthreads();

        const int buf = c & 1;
        const __half* Asm = &smh[buf * HBUF];
        const __half* Bsm = &smh[(2 + buf) * HBUF];

        #pragma unroll
        for (int ks = 0; ks < 2; ks++) {
            const int kb = ks * 16;
            uint32_t af[4][4], bf[4][2];
            #pragma unroll
            for (int mt = 0; mt < 4; mt++) {
                int m0 = wm + mt * 16 + gid;
                af[mt][0] = *reinterpret_cast<const uint32_t*>(&Asm[m0 * KPh + kb + 2 * tig]);
                af[mt][1] = *reinterpret_cast<const uint32_t*>(&Asm[(m0 + 8) * KPh + kb + 2 * tig]);
                af[mt][2] = *reinterpret_cast<const uint32_t*>(&Asm[m0 * KPh + kb + 8 + 2 * tig]);
                af[mt][3] = *reinterpret_cast<const uint32_t*>(&Asm[(m0 + 8) * KPh + kb + 8 + 2 * tig]);
            }
            #pragma unroll
            for (int nt = 0; nt < 4; nt++) {
                int n0 = wn + nt * 8 + gid;
                bf[nt][0] = *reinterpret_cast<const uint32_t*>(&Bsm[n0 * KPh + kb + 2 * tig]);
                bf[nt][1] = *reinterpret_cast<const uint32_t*>(&Bsm[n0 * KPh + kb + 8 + 2 * tig]);
            }
            #pragma unroll
            for (int mt = 0; mt < 4; mt++)
                #pragma unroll
                for (int nt = 0; nt < 4; nt++)
                    mma_f16(acc[mt][nt][0], acc[mt][nt][1],
                            acc[mt][nt][2], acc[mt][nt][3],
                            af[mt][0], af[mt][1], af[mt][2], af[mt][3],
                            bf[nt][0], bf[nt][1]);
        }
        __syncthreads();
    }

    // epilogue
    #pragma unroll
    for (int mt = 0; mt < 4; mt++) {
        #pragma unroll
        for (int nt = 0; nt < 4; nt++) {
            int row0 = bm + wm + mt * 16 + gid;
            int col0 = bn + wn + nt * 8 + tig * 2;
            #pragma unroll
            for (int half = 0; half < 2; half++) {
                int r = row0 + half * 8;
                float v0 = acc[mt][nt][half * 2 + 0];
                float v1 = acc[mt][nt][half * 2 + 1];
                if (bias) { v0 += bias[col0]; v1 += bias[col0 + 1]; }
                if (act == 1) {
                    v0 = 0.5f * v0 * (1.f + erff(v0 * 0.70710678118654752f));
                    v1 = 0.5f * v1 * (1.f + erff(v1 * 0.70710678118654752f));
                } else if (act == 2) {
                    v0 = 1.f / (1.f + expf(-v0));
                    v1 = 1.f / (1.f + expf(-v1));
                }
                size_t o = (size_t)r * Nt + col0;
                if (outhalf) {
                    *reinterpret_cast<__half2*>(&((__half*)Cmat)[o]) =
                        __floats2half2_rn(v0, v1);
                } else {
                    float* Cf = (float*)Cmat;
                    if (resid) {
                        float2 old = *reinterpret_cast<const float2*>(&Cf[o]);
                        v0 += old.x; v1 += old.y;
                    }
                    *reinterpret_cast<float2*>(&Cf[o]) = make_float2(v0, v1);
                }
            }
        }
    }
}

// ---------------- kv = sum_n phi(k)[n,d] * v[n,e] ---------------------------
__global__ void zero_kv_kernel() {
    int i = blockIdx.x * 1024 + threadIdx.x;
    g_kv[i] = 0.f;
}

__global__ void __launch_bounds__(256) kv_kernel() {
    const int bh = blockIdx.x;
    const int chunk = blockIdx.y;
    const int b = bh >> 3, h = bh & 7;
    __shared__ float ks[32][33];
    __shared__ float vs[32][33];
    const int t = threadIdx.x;
    const int d = t >> 3;
    const int e0 = (t & 7) * 4;
    float acc[4] = {0.f, 0.f, 0.f, 0.f};
    const int nbase = chunk * 256;

    for (int nb = 0; nb < 256; nb += 32) {
        #pragma unroll
        for (int i = 0; i < 4; i++) {
            int idx = t + i * 256;
            int row = idx >> 5, col = idx & 31;
            size_t base = ((size_t)(b * Nn + nbase + nb + row)) * (3 * Cc) + h * Dd + col;
            float kvl = g_qkv[base + Cc];
            ks[row][col] = phi_fn(kvl);
            vs[row][col] = g_qkv[base + 2 * Cc];
        }
        __syncthreads();
        #pragma unroll
        for (int nn = 0; nn < 32; nn++) {
            float kd = ks[nn][d];
            #pragma unroll
            for (int j = 0; j < 4; j++)
                acc[j] = fmaf(kd, vs[nn][e0 + j], acc[j]);
        }
        __syncthreads();
    }
    #pragma unroll
    for (int j = 0; j < 4; j++)
        atomicAdd(&g_kv[(size_t)bh * (Dd * Dd) + d * Dd + e0 + j], acc[j]);
}

// ---------------- attn_pre = phi(q) @ kv (fp16 out) --------------------------
__global__ void __launch_bounds__(256) attn_kernel() {
    const int r = blockIdx.x;
    const int b = r >> 12;
    const int c = threadIdx.x;
    __shared__ float pq[Cc];
    float q = g_qkv[(size_t)r * (3 * Cc) + c];
    pq[c] = phi_fn(q);
    __syncthreads();
    const int h = c >> 5, e = c & 31;
    const float* kvp = &g_kv[((size_t)(b * Hh + h)) * (Dd * Dd) + e];
    const float* pqh = &pq[h * Dd];
    float s = 0.f;
    #pragma unroll
    for (int d2 = 0; d2 < Dd; d2++)
        s = fmaf(pqh[d2], kvp[d2 * Dd], s);
    g_attnpreh[(size_t)r * Cc + c] = __float2half_rn(s);
}

// ------- fused: output_mid, new_state (gate), LN3 (fp16 out) -----------------
__global__ void __launch_bounds__(256) fuse_mid_kernel(
    const float* __restrict__ prev,
    const float* __restrict__ w3, const float* __restrict__ b3,
    float* __restrict__ out, float* __restrict__ nstate)
{
    __shared__ float sm[32];
    int r = blockIdx.x;
    int c = threadIdx.x;
    size_t o = (size_t)r * Cc + c;
    float a = g_attnproj[o];
    float om = g_xpos[o] + a;
    out[o] = om;
    float u = g_update[o];
    nstate[o] = prev[o] * (1.f - u) + a * u;
    float2 ss = block_sum2(om, om * om, sm);
    float mu = ss.x * (1.f / Cc);
    float var = ss.y * (1.f / Cc) - mu * mu;
    g_hlnh[o] = __float2half_rn((om - mu) * rsqrtf(var + 1e-5f) * w3[c] + b3[c]);
}

// ---------------- launch ----------------------------------------------------
extern "C" void kernel_launch(void* const* d_in, const int* in_sizes, int n_in,
                              void* d_out, int out_size) {
    const float* input_   = (const float*)d_in[0];
    const float* prev     = (const float*)d_in[1];
    const float* pos      = (const float*)d_in[2];
    const float* n1w      = (const float*)d_in[3];
    const float* n1b      = (const float*)d_in[4];
    const float* n2w      = (const float*)d_in[5];
    const float* n2b      = (const float*)d_in[6];
    const float* n3w      = (const float*)d_in[7];
    const float* n3b      = (const float*)d_in[8];
    const float* qkv_iw   = (const float*)d_in[9];
    const float* qkv_sw   = (const float*)d_in[10];
    const float* proj_w   = (const float*)d_in[11];
    const float* proj_b   = (const float*)d_in[12];
    const float* gate_w   = (const float*)d_in[13];
    const float* gate_b   = (const float*)d_in[14];
    const float* fc1_w    = (const float*)d_in[15];
    const float* fc1_b    = (const float*)d_in[16];
    const float* fc2_w    = (const float*)d_in[17];
    const float* fc2_b    = (const float*)d_in[18];

    float* out    = (float*)d_out;
    float* nstate = out + (size_t)out_size / 2;

    __half *p_wh;
    float *p_qkv, *p_attnproj, *p_update;
    __half *p_xlnh, *p_slnh, *p_xh, *p_sh, *p_attnpreh, *p_hlnh, *p_fc1h;
    cudaGetSymbolAddress((void**)&p_wh, g_wh);
    cudaGetSymbolAddress((void**)&p_qkv, g_qkv);
    cudaGetSymbolAddress((void**)&p_attnproj, g_attnproj);
    cudaGetSymbolAddress((void**)&p_update, g_update);
    cudaGetSymbolAddress((void**)&p_xlnh, g_xlnh);
    cudaGetSymbolAddress((void**)&p_slnh, g_slnh);
    cudaGetSymbolAddress((void**)&p_xh, g_xh);
    cudaGetSymbolAddress((void**)&p_sh, g_sh);
    cudaGetSymbolAddress((void**)&p_attnpreh, g_attnpreh);
    cudaGetSymbolAddress((void**)&p_hlnh, g_hlnh);
    cudaGetSymbolAddress((void**)&p_fc1h, g_fc1h);

    cudaFuncSetAttribute(mma_gemm_kernel,
                         cudaFuncAttributeMaxDynamicSharedMemorySize,
                         GEMM_SMEM_BYTES);

    // 0) weights -> fp16
    w2h_kernel<<<(196608/4 + 255)/256, 256>>>(qkv_iw, p_wh + WOFF_QKVI, 196608/4);
    w2h_kernel<<<(196608/4 + 255)/256, 256>>>(qkv_sw, p_wh + WOFF_QKVS, 196608/4);
    w2h_kernel<<<(65536/4  + 255)/256, 256>>>(proj_w, p_wh + WOFF_PROJ, 65536/4);
    w2h_kernel<<<(131072/4 + 255)/256, 256>>>(gate_w, p_wh + WOFF_GATE, 131072/4);
    w2h_kernel<<<(262144/4 + 255)/256, 256>>>(fc1_w,  p_wh + WOFF_FC1,  262144/4);
    w2h_kernel<<<(262144/4 + 255)/256, 256>>>(fc2_w,  p_wh + WOFF_FC2,  262144/4);

    // 1) x_pos + LN1 + LN2 + fp16 copies
    ln_pre_kernel<<<Mrows, 256>>>(input_, prev, pos, n1w, n1b, n2w, n2b);

    // 2) qkv = x_ln @ Wi^T + s_ln @ Ws^T   [M, 768] fp32 out
    mma_gemm_kernel<<<dim3(768 / GBN, Mrows / GBM), 256, GEMM_SMEM_BYTES>>>(
        p_xlnh, p_slnh, p_wh + WOFF_QKVI, p_wh + WOFF_QKVS, nullptr, p_qkv,
        3 * Cc, Cc, Cc, 0, 0, 0);

    // 3) kv[b,h,d,e]
    zero_kv_kernel<<<64, 1024>>>();
    kv_kernel<<<dim3(Bb * Hh, 16), 256>>>();

    // 4) attn_pre = phi_q @ kv (fp16 out)
    attn_kernel<<<Mrows, 256>>>();

    // 5) proj (fp32 out)
    mma_gemm_kernel<<<dim3(Cc / GBN, Mrows / GBM), 256, GEMM_SMEM_BYTES>>>(
        p_attnpreh, nullptr, p_wh + WOFF_PROJ, nullptr, proj_b, p_attnproj,
        Cc, Cc, Cc, 0, 0, 0);

    // 6) gate: update = sigmoid([input_, prev] @ gate_w^T + gate_b) (fp32 out)
    mma_gemm_kernel<<<dim3(Cc / GBN, Mrows / GBM), 256, GEMM_SMEM_BYTES>>>(
        p_xh, p_sh, p_wh + WOFF_GATE, p_wh + WOFF_GATE + Cc, gate_b, p_update,
        Cc, Cc, 2 * Cc, 2, 0, 0);

    // 7) output_mid -> d_out, new_state, LN3 -> g_hlnh
    fuse_mid_kernel<<<Mrows, 256>>>(prev, n3w, n3b, out, nstate);

    // 8) fc1 with exact-gelu epilogue (fp16 out)
    mma_gemm_kernel<<<dim3(HID / GBN, Mrows / GBM), 256, GEMM_SMEM_BYTES>>>(
        p_hlnh, nullptr, p_wh + WOFF_FC1, nullptr, fc1_b, p_fc1h,
        HID, Cc, Cc, 1, 0, 1);

    // 9) fc2, accumulate into output residual (fp32)
    mma_gemm_kernel<<<dim3(Cc / GBN, Mrows / GBM), 256, GEMM_SMEM_BYTES>>>(
        p_fc1h, nullptr, p_wh + WOFF_FC2, nullptr, fc2_b, out,
        Cc, HID, HID, 0, 1, 0);
}

// round 8
// speedup vs baseline: 3.5788x; 1.0467x over previous
#include <cuda_runtime.h>
#include <cuda_fp16.h>
#include <cstdint>
#include <math.h>

// Problem constants
#define Bb 8
#define Nn 4096
#define Cc 256
#define Hh 8
#define Dd 32
#define HID 1024
#define Mrows (Bb * Nn)            // 32768
#define ROWSZ ((size_t)Mrows * Cc) // 8388608

// ---------------- scratch (device globals; no allocations allowed) ---------
__device__ float  g_xpos[ROWSZ];
__device__ __half g_xlnh[ROWSZ];
__device__ __half g_slnh[ROWSZ];
__device__ __half g_xh[ROWSZ];
__device__ __half g_sh[ROWSZ];
__device__ __half g_qkvh[(size_t)Mrows * 3 * Cc];
__device__ __half g_attnpreh[ROWSZ];
__device__ float  g_attnproj[ROWSZ];
__device__ __half g_updateh[ROWSZ];
__device__ __half g_hlnh[ROWSZ];
__device__ __half g_fc1h[(size_t)Mrows * HID];
__device__ float  g_kv[Bb * Hh * Dd * Dd];
// fp16 weights, concatenated (offsets in halves)
#define WOFF_QKVI 0
#define WOFF_QKVS 196608
#define WOFF_PROJ 393216
#define WOFF_GATE 458752
#define WOFF_FC1  589824
#define WOFF_FC2  851968
#define WTOTAL    1114112
__device__ __half g_wh[WTOTAL];

// ---------------- misc helpers ----------------------------------------------
__device__ __forceinline__ float2 block_sum2(float a, float b, float* sm) {
    #pragma unroll
    for (int o = 16; o > 0; o >>= 1) {
        a += __shfl_down_sync(0xffffffffu, a, o);
        b += __shfl_down_sync(0xffffffffu, b, o);
    }
    int w = threadIdx.x >> 5, l = threadIdx.x & 31;
    if (l == 0) { sm[w] = a; sm[8 + w] = b; }
    __syncthreads();
    if (w == 0) {
        a = sm[l & 7]; b = sm[8 + (l & 7)];
        #pragma unroll
        for (int o = 4; o > 0; o >>= 1) {
            a += __shfl_down_sync(0xffffffffu, a, o);
            b += __shfl_down_sync(0xffffffffu, b, o);
        }
        if (l == 0) { sm[16] = a; sm[17] = b; }
    }
    __syncthreads();
    return make_float2(sm[16], sm[17]);
}

__device__ __forceinline__ float phi_fn(float x) {
    return x > 0.f ? x + 1.f : expf(x);
}

__device__ __forceinline__ uint32_t smem_to_u32(const void* p) {
    uint32_t a;
    asm("{ .reg .u64 t; cvta.to.shared.u64 t, %1; cvt.u32.u64 %0, t; }"
        : "=r"(a) : "l"(p));
    return a;
}

__device__ __forceinline__ void cpasync16(uint32_t smem_addr, const void* gptr) {
    asm volatile("cp.async.cg.shared.global [%0], [%1], 16;"
        :: "r"(smem_addr), "l"(gptr) : "memory");
}
__device__ __forceinline__ void cpasync_commit() {
    asm volatile("cp.async.commit_group;" ::: "memory");
}
template <int N>
__device__ __forceinline__ void cpasync_wait() {
    asm volatile("cp.async.wait_group %0;" :: "n"(N) : "memory");
}

// fp16 m16n8k16 mma: D (f32x4) += A(f16x2 x4) @ B(f16x2 x2)
__device__ __forceinline__ void mma_f16(
    float& c0, float& c1, float& c2, float& c3,
    uint32_t a0, uint32_t a1, uint32_t a2, uint32_t a3,
    uint32_t b0, uint32_t b1)
{
    asm volatile(
        "mma.sync.aligned.m16n8k16.row.col.f32.f16.f16.f32 "
        "{%0,%1,%2,%3}, {%4,%5,%6,%7}, {%8,%9}, {%0,%1,%2,%3};"
        : "+f"(c0), "+f"(c1), "+f"(c2), "+f"(c3)
        : "r"(a0), "r"(a1), "r"(a2), "r"(a3), "r"(b0), "r"(b1));
}

// ---------------- all weights fp32 -> fp16, single kernel --------------------
__global__ void __launch_bounds__(256) w2h_all_kernel(
    const float* __restrict__ qkvi, const float* __restrict__ qkvs,
    const float* __restrict__ proj, const float* __restrict__ gate,
    const float* __restrict__ fc1,  const float* __restrict__ fc2)
{
    int i = blockIdx.x * 256 + threadIdx.x;   // float4 index, 278528 total
    const float* src; int local; int woff;
    if      (i < 49152)  { src = qkvi; local = i;          woff = WOFF_QKVI; }
    else if (i < 98304)  { src = qkvs; local = i - 49152;  woff = WOFF_QKVS; }
    else if (i < 114688) { src = proj; local = i - 98304;  woff = WOFF_PROJ; }
    else if (i < 147456) { src = gate; local = i - 114688; woff = WOFF_GATE; }
    else if (i < 212992) { src = fc1;  local = i - 147456; woff = WOFF_FC1;  }
    else                 { src = fc2;  local = i - 212992; woff = WOFF_FC2;  }
    float4 v = reinterpret_cast<const float4*>(src)[local];
    __half2* d = reinterpret_cast<__half2*>(&g_wh[woff]) + 2 * local;
    d[0] = __floats2half2_rn(v.x, v.y);
    d[1] = __floats2half2_rn(v.z, v.w);
}

// ---------------- kernel 1: x_pos, LN1, LN2, fp16 copies ---------------------
__global__ void __launch_bounds__(256) ln_pre_kernel(
    const float* __restrict__ input_, const float* __restrict__ prev,
    const float* __restrict__ pos,
    const float* __restrict__ w1, const float* __restrict__ b1,
    const float* __restrict__ w2, const float* __restrict__ b2)
{
    __shared__ float sm[32];
    int r = blockIdx.x;
    int c = threadIdx.x;
    int n = r & (Nn - 1);
    size_t o = (size_t)r * Cc + c;

    float xin = input_[o];
    float x = xin + pos[(size_t)n * Cc + c];
    g_xpos[o] = x;
    g_xh[o] = __float2half_rn(xin);
    float2 ss = block_sum2(x, x * x, sm);
    float mu = ss.x * (1.f / Cc);
    float var = ss.y * (1.f / Cc) - mu * mu;
    g_xlnh[o] = __float2half_rn((x - mu) * rsqrtf(var + 1e-5f) * w1[c] + b1[c]);

    float s = prev[o];
    g_sh[o] = __float2half_rn(s);
    ss = block_sum2(s, s * s, sm);
    mu = ss.x * (1.f / Cc);
    var = ss.y * (1.f / Cc) - mu * mu;
    g_slnh[o] = __float2half_rn((s - mu) * rsqrtf(var + 1e-5f) * w2[c] + b2[c]);
}

// ---------------- fp16 mma GEMM: C = sum_p A_p @ W_p^T (+bias,act) ----------
// Block tile 128x128, warp grid 2x4 (warp tile 64x32), K chunk = 32 halves.
// smem m-major [row][KPh=40] fp16 (conflict-free frags), 3-stage cp.async.
// act: 0 none, 1 exact gelu, 2 sigmoid. resid: C += v. outhalf: fp16 store.
#define GBM 128
#define GBN 128
#define GKC 32
#define KPh 40
#define HBUF (GBM * KPh)                   // 5120 halves per buffer
#define NSTG 3
#define GEMM_SMEM_BYTES (2 * NSTG * HBUF * 2)  // 61440 B

__global__ void __launch_bounds__(256) mma_gemm_kernel(
    const __half* __restrict__ A0, const __half* __restrict__ A1,
    const __half* __restrict__ W0, const __half* __restrict__ W1,
    const float* __restrict__ bias, void* __restrict__ Cmat,
    int Nt, int K, int ldw, int act, int resid, int outhalf)
{
    extern __shared__ __half smh[];
    const uint32_t sbase = smem_to_u32(smh);
    const int tid = threadIdx.x;
    const int bm = blockIdx.y * GBM;
    const int bn = blockIdx.x * GBN;
    const int wid = tid >> 5, lane = tid & 31;
    const int gid = lane >> 2, tig = lane & 3;
    const int wm = (wid >> 2) * 64;
    const int wn = (wid & 3) * 32;

    float acc[4][4][4];
    #pragma unroll
    for (int mt = 0; mt < 4; mt++)
        #pragma unroll
        for (int nt = 0; nt < 4; nt++)
            #pragma unroll
            for (int q = 0; q < 4; q++) acc[mt][nt][q] = 0.f;

    const int kchunks = K / GKC;
    const int npairs = (A1 != nullptr) ? 2 : 1;
    const int nchunks = kchunks * npairs;

    auto issue = [&](int c) {
        const int buf = c % NSTG;
        const int p = c / kchunks;
        const int k0 = (c - p * kchunks) * GKC;
        const __half* __restrict__ A = p ? A1 : A0;
        const __half* __restrict__ W = p ? W1 : W0;
        #pragma unroll
        for (int i = 0; i < 2; i++) {
            int f = tid + i * 256;
            int row = f >> 2, seg = f & 3;
            uint32_t da = sbase + (uint32_t)((buf * HBUF + row * KPh + seg * 8) * 2);
            cpasync16(da, &A[(size_t)(bm + row) * K + k0 + seg * 8]);
            uint32_t db = sbase + (uint32_t)(((NSTG + buf) * HBUF + row * KPh + seg * 8) * 2);
            cpasync16(db, &W[(size_t)(bn + row) * ldw + k0 + seg * 8]);
        }
        cpasync_commit();
    };

    issue(0);
    if (nchunks > 1) issue(1);

    for (int c = 0; c < nchunks; c++) {
        if (c + 2 < nchunks) {
            issue(c + 2);
            cpasync_wait<2>();
        } else if (c + 1 < nchunks) {
            cpasync_wait<1>();
        } else {
            cpasync_wait<0>();
        }
        __syncthreads();

        const int buf = c % NSTG;
        const __half* Asm = &smh[buf * HBUF];
        const __half* Bsm = &smh[(NSTG + buf) * HBUF];

        #pragma unroll
        for (int ks = 0; ks < 2; ks++) {
            const int kb = ks * 16;
            uint32_t af[4][4], bf[4][2];
            #pragma unroll
            for (int mt = 0; mt < 4; mt++) {
                int m0 = wm + mt * 16 + gid;
                af[mt][0] = *reinterpret_cast<const uint32_t*>(&Asm[m0 * KPh + kb + 2 * tig]);
                af[mt][1] = *reinterpret_cast<const uint32_t*>(&Asm[(m0 + 8) * KPh + kb + 2 * tig]);
                af[mt][2] = *reinterpret_cast<const uint32_t*>(&Asm[m0 * KPh + kb + 8 + 2 * tig]);
                af[mt][3] = *reinterpret_cast<const uint32_t*>(&Asm[(m0 + 8) * KPh + kb + 8 + 2 * tig]);
            }
            #pragma unroll
            for (int nt = 0; nt < 4; nt++) {
                int n0 = wn + nt * 8 + gid;
                bf[nt][0] = *reinterpret_cast<const uint32_t*>(&Bsm[n0 * KPh + kb + 2 * tig]);
                bf[nt][1] = *reinterpret_cast<const uint32_t*>(&Bsm[n0 * KPh + kb + 8 + 2 * tig]);
            }
            #pragma unroll
            for (int mt = 0; mt < 4; mt++)
                #pragma unroll
                for (int nt = 0; nt < 4; nt++)
                    mma_f16(acc[mt][nt][0], acc[mt][nt][1],
                            acc[mt][nt][2], acc[mt][nt][3],
                            af[mt][0], af[mt][1], af[mt][2], af[mt][3],
                            bf[nt][0], bf[nt][1]);
        }
        __syncthreads();
    }

    // epilogue
    #pragma unroll
    for (int mt = 0; mt < 4; mt++) {
        #pragma unroll
        for (int nt = 0; nt < 4; nt++) {
            int row0 = bm + wm + mt * 16 + gid;
            int col0 = bn + wn + nt * 8 + tig * 2;
            #pragma unroll
            for (int half = 0; half < 2; half++) {
                int r = row0 + half * 8;
                float v0 = acc[mt][nt][half * 2 + 0];
                float v1 = acc[mt][nt][half * 2 + 1];
                if (bias) { v0 += bias[col0]; v1 += bias[col0 + 1]; }
                if (act == 1) {
                    v0 = 0.5f * v0 * (1.f + erff(v0 * 0.70710678118654752f));
                    v1 = 0.5f * v1 * (1.f + erff(v1 * 0.70710678118654752f));
                } else if (act == 2) {
                    v0 = 1.f / (1.f + expf(-v0));
                    v1 = 1.f / (1.f + expf(-v1));
                }
                size_t o = (size_t)r * Nt + col0;
                if (outhalf) {
                    *reinterpret_cast<__half2*>(&((__half*)Cmat)[o]) =
                        __floats2half2_rn(v0, v1);
                } else {
                    float* Cf = (float*)Cmat;
                    if (resid) {
                        float2 old = *reinterpret_cast<const float2*>(&Cf[o]);
                        v0 += old.x; v1 += old.y;
                    }
                    *reinterpret_cast<float2*>(&Cf[o]) = make_float2(v0, v1);
                }
            }
        }
    }
}

// ---------------- kv = sum_n phi(k)[n,d] * v[n,e] (fp16 input) ---------------
__global__ void zero_kv_kernel() {
    int i = blockIdx.x * 1024 + threadIdx.x;
    g_kv[i] = 0.f;
}

__global__ void __launch_bounds__(256) kv_kernel() {
    const int bh = blockIdx.x;
    const int chunk = blockIdx.y;
    const int b = bh >> 3, h = bh & 7;
    __shared__ float ks[32][33];
    __shared__ float vs[32][33];
    const int t = threadIdx.x;
    const int d = t >> 3;
    const int e0 = (t & 7) * 4;
    float acc[4] = {0.f, 0.f, 0.f, 0.f};
    const int nbase = chunk * 256;

    for (int nb = 0; nb < 256; nb += 32) {
        #pragma unroll
        for (int i = 0; i < 2; i++) {
            int idx = t + i * 256;
            int row = idx >> 4, cp = (idx & 15) * 2;
            size_t base = ((size_t)(b * Nn + nbase + nb + row)) * (3 * Cc) + h * Dd + cp;
            float2 kf = __half22float2(*reinterpret_cast<const __half2*>(&g_qkvh[base + Cc]));
            float2 vf = __half22float2(*reinterpret_cast<const __half2*>(&g_qkvh[base + 2 * Cc]));
            ks[row][cp]     = phi_fn(kf.x);
            ks[row][cp + 1] = phi_fn(kf.y);
            vs[row][cp]     = vf.x;
            vs[row][cp + 1] = vf.y;
        }
        __syncthreads();
        #pragma unroll
        for (int nn = 0; nn < 32; nn++) {
            float kd = ks[nn][d];
            #pragma unroll
            for (int j = 0; j < 4; j++)
                acc[j] = fmaf(kd, vs[nn][e0 + j], acc[j]);
        }
        __syncthreads();
    }
    #pragma unroll
    for (int j = 0; j < 4; j++)
        atomicAdd(&g_kv[(size_t)bh * (Dd * Dd) + d * Dd + e0 + j], acc[j]);
}

// ---------------- attn_pre = phi(q) @ kv (fp16 in/out) -----------------------
__global__ void __launch_bounds__(256) attn_kernel() {
    const int r = blockIdx.x;
    const int b = r >> 12;
    const int c = threadIdx.x;
    __shared__ float pq[Cc];
    float q = __half2float(g_qkvh[(size_t)r * (3 * Cc) + c]);
    pq[c] = phi_fn(q);
    __syncthreads();
    const int h = c >> 5, e = c & 31;
    const float* kvp = &g_kv[((size_t)(b * Hh + h)) * (Dd * Dd) + e];
    const float* pqh = &pq[h * Dd];
    float s = 0.f;
    #pragma unroll
    for (int d2 = 0; d2 < Dd; d2++)
        s = fmaf(pqh[d2], kvp[d2 * Dd], s);
    g_attnpreh[(size_t)r * Cc + c] = __float2half_rn(s);
}

// ------- fused: output_mid, new_state (gate), LN3 (fp16 out) -----------------
__global__ void __launch_bounds__(256) fuse_mid_kernel(
    const float* __restrict__ prev,
    const float* __restrict__ w3, const float* __restrict__ b3,
    float* __restrict__ out, float* __restrict__ nstate)
{
    __shared__ float sm[32];
    int r = blockIdx.x;
    int c = threadIdx.x;
    size_t o = (size_t)r * Cc + c;
    float a = g_attnproj[o];
    float om = g_xpos[o] + a;
    out[o] = om;
    float u = __half2float(g_updateh[o]);
    nstate[o] = prev[o] * (1.f - u) + a * u;
    float2 ss = block_sum2(om, om * om, sm);
    float mu = ss.x * (1.f / Cc);
    float var = ss.y * (1.f / Cc) - mu * mu;
    g_hlnh[o] = __float2half_rn((om - mu) * rsqrtf(var + 1e-5f) * w3[c] + b3[c]);
}

// ---------------- launch ----------------------------------------------------
extern "C" void kernel_launch(void* const* d_in, const int* in_sizes, int n_in,
                              void* d_out, int out_size) {
    const float* input_   = (const float*)d_in[0];
    const float* prev     = (const float*)d_in[1];
    const float* pos      = (const float*)d_in[2];
    const float* n1w      = (const float*)d_in[3];
    const float* n1b      = (const float*)d_in[4];
    const float* n2w      = (const float*)d_in[5];
    const float* n2b      = (const float*)d_in[6];
    const float* n3w      = (const float*)d_in[7];
    const float* n3b      = (const float*)d_in[8];
    const float* qkv_iw   = (const float*)d_in[9];
    const float* qkv_sw   = (const float*)d_in[10];
    const float* proj_w   = (const float*)d_in[11];
    const float* proj_b   = (const float*)d_in[12];
    const float* gate_w   = (const float*)d_in[13];
    const float* gate_b   = (const float*)d_in[14];
    const float* fc1_w    = (const float*)d_in[15];
    const float* fc1_b    = (const float*)d_in[16];
    const float* fc2_w    = (const float*)d_in[17];
    const float* fc2_b    = (const float*)d_in[18];

    float* out    = (float*)d_out;
    float* nstate = out + (size_t)out_size / 2;

    __half *p_wh;
    float *p_attnproj;
    __half *p_xlnh, *p_slnh, *p_xh, *p_sh, *p_qkvh, *p_attnpreh, *p_updateh, *p_hlnh, *p_fc1h;
    cudaGetSymbolAddress((void**)&p_wh, g_wh);
    cudaGetSymbolAddress((void**)&p_attnproj, g_attnproj);
    cudaGetSymbolAddress((void**)&p_xlnh, g_xlnh);
    cudaGetSymbolAddress((void**)&p_slnh, g_slnh);
    cudaGetSymbolAddress((void**)&p_xh, g_xh);
    cudaGetSymbolAddress((void**)&p_sh, g_sh);
    cudaGetSymbolAddress((void**)&p_qkvh, g_qkvh);
    cudaGetSymbolAddress((void**)&p_attnpreh, g_attnpreh);
    cudaGetSymbolAddress((void**)&p_updateh, g_updateh);
    cudaGetSymbolAddress((void**)&p_hlnh, g_hlnh);
    cudaGetSymbolAddress((void**)&p_fc1h, g_fc1h);

    cudaFuncSetAttribute(mma_gemm_kernel,
                         cudaFuncAttributeMaxDynamicSharedMemorySize,
                         GEMM_SMEM_BYTES);

    // 0) all weights -> fp16 (one kernel)
    w2h_all_kernel<<<1088, 256>>>(qkv_iw, qkv_sw, proj_w, gate_w, fc1_w, fc2_w);

    // 1) x_pos + LN1 + LN2 + fp16 copies
    ln_pre_kernel<<<Mrows, 256>>>(input_, prev, pos, n1w, n1b, n2w, n2b);

    // 2) qkv = x_ln @ Wi^T + s_ln @ Ws^T   [M, 768] fp16 out
    mma_gemm_kernel<<<dim3(768 / GBN, Mrows / GBM), 256, GEMM_SMEM_BYTES>>>(
        p_xlnh, p_slnh, p_wh + WOFF_QKVI, p_wh + WOFF_QKVS, nullptr, p_qkvh,
        3 * Cc, Cc, Cc, 0, 0, 1);

    // 3) kv[b,h,d,e]
    zero_kv_kernel<<<64, 1024>>>();
    kv_kernel<<<dim3(Bb * Hh, 16), 256>>>();

    // 4) attn_pre = phi_q @ kv (fp16 out)
    attn_kernel<<<Mrows, 256>>>();

    // 5) proj (fp32 out)
    mma_gemm_kernel<<<dim3(Cc / GBN, Mrows / GBM), 256, GEMM_SMEM_BYTES>>>(
        p_attnpreh, nullptr, p_wh + WOFF_PROJ, nullptr, proj_b, p_attnproj,
        Cc, Cc, Cc, 0, 0, 0);

    // 6) gate: update = sigmoid([input_, prev] @ gate_w^T + gate_b) (fp16 out)
    mma_gemm_kernel<<<dim3(Cc / GBN, Mrows / GBM), 256, GEMM_SMEM_BYTES>>>(
        p_xh, p_sh, p_wh + WOFF_GATE, p_wh + WOFF_GATE + Cc, gate_b, p_updateh,
        Cc, Cc, 2 * Cc, 2, 0, 1);

    // 7) output_mid -> d_out, new_state, LN3 -> g_hlnh
    fuse_mid_kernel<<<Mrows, 256>>>(prev, n3w, n3b, out, nstate);

    // 8) fc1 with exact-gelu epilogue (fp16 out)
    mma_gemm_kernel<<<dim3(HID / GBN, Mrows / GBM), 256, GEMM_SMEM_BYTES>>>(
        p_hlnh, nullptr, p_wh + WOFF_FC1, nullptr, fc1_b, p_fc1h,
        HID, Cc, Cc, 1, 0, 1);

    // 9) fc2, accumulate into output residual (fp32)
    mma_gemm_kernel<<<dim3(Cc / GBN, Mrows / GBM), 256, GEMM_SMEM_BYTES>>>(
        p_fc1h, nullptr, p_wh + WOFF_FC2, nullptr, fc2_b, out,
        Cc, HID, HID, 0, 1, 0);
}